// round 4
// baseline (speedup 1.0000x reference)
#include <cuda_runtime.h>
#include <cuda_bf16.h>
#include <cstdint>

// Problem shape (fixed by the dataset): x[4096,1024], positive[4096,1024], negative[8192,1024]
#define M_ROWS 4096
#define N_ROWS 8192
#define DIM    1024
#define NBLK   (N_ROWS / 128)   // 64 column tiles
#define EPSF   1e-8f

// ---------------- scratch (no allocations allowed) ----------------
__device__ __nv_bfloat16 g_Xb[(size_t)M_ROWS * DIM];   // 8 MB
__device__ __nv_bfloat16 g_Nb[(size_t)N_ROWS * DIM];   // 16 MB
__device__ float g_nx[M_ROWS];
__device__ float g_sim[M_ROWS];
__device__ float g_nn[N_ROWS];
__device__ float g_partial[(size_t)M_ROWS * NBLK];     // 1 MB

// ---------------- kernel 1: norms of x & positive, sim, x->bf16 ----------------
__global__ void prep_xp(const float* __restrict__ x, const float* __restrict__ p) {
    int row = blockIdx.x;
    int t = threadIdx.x;                     // 256 threads, 4 floats each
    const float4 xv = ((const float4*)(x + (size_t)row * DIM))[t];
    const float4 pv = ((const float4*)(p + (size_t)row * DIM))[t];

    __nv_bfloat162* ob = (__nv_bfloat162*)(g_Xb + (size_t)row * DIM);
    ob[2 * t]     = __floats2bfloat162_rn(xv.x, xv.y);
    ob[2 * t + 1] = __floats2bfloat162_rn(xv.z, xv.w);

    float sx = xv.x * xv.x + xv.y * xv.y + xv.z * xv.z + xv.w * xv.w;
    float sp = pv.x * pv.x + pv.y * pv.y + pv.z * pv.z + pv.w * pv.w;
    float dp = xv.x * pv.x + xv.y * pv.y + xv.z * pv.z + xv.w * pv.w;

    #pragma unroll
    for (int o = 16; o > 0; o >>= 1) {
        sx += __shfl_down_sync(0xffffffffu, sx, o);
        sp += __shfl_down_sync(0xffffffffu, sp, o);
        dp += __shfl_down_sync(0xffffffffu, dp, o);
    }
    __shared__ float ssx[8], ssp[8], sdp[8];
    int w = t >> 5, l = t & 31;
    if (l == 0) { ssx[w] = sx; ssp[w] = sp; sdp[w] = dp; }
    __syncthreads();
    if (t == 0) {
        float ax = 0.f, ap = 0.f, ad = 0.f;
        #pragma unroll
        for (int i = 0; i < 8; i++) { ax += ssx[i]; ap += ssp[i]; ad += sdp[i]; }
        float nx = sqrtf(ax), np = sqrtf(ap);
        g_nx[row]  = nx;
        g_sim[row] = ad / fmaxf(nx * np, EPSF);
    }
}

// ---------------- kernel 2: norms of negative, negative->bf16 ----------------
__global__ void prep_neg(const float* __restrict__ n) {
    int row = blockIdx.x;
    int t = threadIdx.x;
    const float4 nv = ((const float4*)(n + (size_t)row * DIM))[t];

    __nv_bfloat162* ob = (__nv_bfloat162*)(g_Nb + (size_t)row * DIM);
    ob[2 * t]     = __floats2bfloat162_rn(nv.x, nv.y);
    ob[2 * t + 1] = __floats2bfloat162_rn(nv.z, nv.w);

    float sn = nv.x * nv.x + nv.y * nv.y + nv.z * nv.z + nv.w * nv.w;
    #pragma unroll
    for (int o = 16; o > 0; o >>= 1) sn += __shfl_down_sync(0xffffffffu, sn, o);
    __shared__ float ssn[8];
    int w = t >> 5, l = t & 31;
    if (l == 0) ssn[w] = sn;
    __syncthreads();
    if (t == 0) {
        float a = 0.f;
        #pragma unroll
        for (int i = 0; i < 8; i++) a += ssn[i];
        g_nn[row] = sqrtf(a);
    }
}

// ---------------- kernel 3: fused bf16 GEMM + exp-rowsum epilogue ----------------
// C = Xb (4096x1024) * Nb^T (1024x8192). Block tile 128x128, K-tile 32, 8 warps (4m x 2n),
// warp tile 32x64 via m16n8k16. Smem rows padded to 40 bf16 (80 B) -> conflict-free ldmatrix.
__device__ __forceinline__ uint32_t smem_u32(const void* p) {
    return (uint32_t)__cvta_generic_to_shared(p);
}

__global__ void __launch_bounds__(256, 2) gemm_fused() {
    constexpr int LDA = 40;
    __shared__ __nv_bfloat16 As[2][128 * LDA];
    __shared__ __nv_bfloat16 Bs[2][128 * LDA];
    __shared__ float epi[128][2];

    const int tid = threadIdx.x;
    const int mBase = blockIdx.y * 128;
    const int nBase = blockIdx.x * 128;

    // cp.async mapping: 512 16B-chunks per tile, 2 per thread
    const int lrow = tid >> 2;            // 0..63
    const int lcol = (tid & 3) * 8;       // element offset of the 16B chunk
    const __nv_bfloat16* srcA0 = g_Xb + (size_t)(mBase + lrow) * DIM + lcol;
    const __nv_bfloat16* srcB0 = g_Nb + (size_t)(nBase + lrow) * DIM + lcol;

    const int warp = tid >> 5, lane = tid & 31;
    const int warpM = warp >> 1, warpN = warp & 1;
    const int g = lane >> 2, tg = lane & 3;

    float acc[2][8][4];
    #pragma unroll
    for (int mi = 0; mi < 2; mi++)
        #pragma unroll
        for (int ni = 0; ni < 8; ni++)
            #pragma unroll
            for (int q = 0; q < 4; q++) acc[mi][ni][q] = 0.f;

    // precomputed ldmatrix smem row/col offsets (stage-independent parts)
    const int aRow = warpM * 32 + (lane & 15);
    const int aColOff = (lane >> 4) << 3;
    const int bRow = warpN * 64 + (lane & 7) + ((lane >> 4) << 3);
    const int bColOff = ((lane >> 3) & 1) << 3;

    auto load_stage = [&](int s, int k0) {
        #pragma unroll
        for (int it = 0; it < 2; it++) {
            int r = lrow + it * 64;
            uint32_t da = smem_u32(&As[s][r * LDA + lcol]);
            const void* sa = (const void*)(srcA0 + (size_t)it * 64 * DIM + k0);
            asm volatile("cp.async.cg.shared.global [%0], [%1], 16;\n" :: "r"(da), "l"(sa));
            uint32_t db = smem_u32(&Bs[s][r * LDA + lcol]);
            const void* sb = (const void*)(srcB0 + (size_t)it * 64 * DIM + k0);
            asm volatile("cp.async.cg.shared.global [%0], [%1], 16;\n" :: "r"(db), "l"(sb));
        }
    };

    load_stage(0, 0);
    asm volatile("cp.async.commit_group;\n" ::);

    const int NK = DIM / 32;   // 32 K-tiles
    for (int k = 0; k < NK; k++) {
        asm volatile("cp.async.wait_group 0;\n" ::);
        __syncthreads();
        if (k + 1 < NK) {
            load_stage((k + 1) & 1, (k + 1) * 32);
            asm volatile("cp.async.commit_group;\n" ::);
        }
        const int s = k & 1;
        #pragma unroll
        for (int kk = 0; kk < 32; kk += 16) {
            uint32_t ar[2][4];
            #pragma unroll
            for (int mi = 0; mi < 2; mi++) {
                uint32_t addr = smem_u32(&As[s][(aRow + mi * 16) * LDA + kk + aColOff]);
                asm volatile("ldmatrix.sync.aligned.m8n8.x4.shared.b16 {%0,%1,%2,%3}, [%4];\n"
                             : "=r"(ar[mi][0]), "=r"(ar[mi][1]), "=r"(ar[mi][2]), "=r"(ar[mi][3])
                             : "r"(addr));
            }
            uint32_t br[8][2];
            #pragma unroll
            for (int nb = 0; nb < 4; nb++) {
                uint32_t addr = smem_u32(&Bs[s][(bRow + nb * 16) * LDA + kk + bColOff]);
                uint32_t r0, r1, r2, r3;
                asm volatile("ldmatrix.sync.aligned.m8n8.x4.shared.b16 {%0,%1,%2,%3}, [%4];\n"
                             : "=r"(r0), "=r"(r1), "=r"(r2), "=r"(r3) : "r"(addr));
                br[2 * nb][0] = r0; br[2 * nb][1] = r1;
                br[2 * nb + 1][0] = r2; br[2 * nb + 1][1] = r3;
            }
            #pragma unroll
            for (int mi = 0; mi < 2; mi++)
                #pragma unroll
                for (int ni = 0; ni < 8; ni++) {
                    float* d = acc[mi][ni];
                    asm volatile(
                        "mma.sync.aligned.m16n8k16.row.col.f32.bf16.bf16.f32 "
                        "{%0,%1,%2,%3}, {%4,%5,%6,%7}, {%8,%9}, {%0,%1,%2,%3};\n"
                        : "+f"(d[0]), "+f"(d[1]), "+f"(d[2]), "+f"(d[3])
                        : "r"(ar[mi][0]), "r"(ar[mi][1]), "r"(ar[mi][2]), "r"(ar[mi][3]),
                          "r"(br[ni][0]), "r"(br[ni][1]));
                }
        }
        __syncthreads();
    }

    // ---- epilogue: exp(cos) and per-row sum over this block's 128 columns ----
    float nxv[2][2];
    #pragma unroll
    for (int mi = 0; mi < 2; mi++) {
        int r0 = mBase + warpM * 32 + mi * 16 + g;
        nxv[mi][0] = g_nx[r0];
        nxv[mi][1] = g_nx[r0 + 8];
    }
    float nnv[8][2];
    #pragma unroll
    for (int ni = 0; ni < 8; ni++) {
        int c0 = nBase + warpN * 64 + ni * 8 + 2 * tg;
        nnv[ni][0] = g_nn[c0];
        nnv[ni][1] = g_nn[c0 + 1];
    }

    float rs[2][2] = {{0.f, 0.f}, {0.f, 0.f}};
    #pragma unroll
    for (int mi = 0; mi < 2; mi++)
        #pragma unroll
        for (int ni = 0; ni < 8; ni++) {
            const float* d = acc[mi][ni];
            rs[mi][0] += __expf(__fdividef(d[0], fmaxf(nxv[mi][0] * nnv[ni][0], EPSF)))
                       + __expf(__fdividef(d[1], fmaxf(nxv[mi][0] * nnv[ni][1], EPSF)));
            rs[mi][1] += __expf(__fdividef(d[2], fmaxf(nxv[mi][1] * nnv[ni][0], EPSF)))
                       + __expf(__fdividef(d[3], fmaxf(nxv[mi][1] * nnv[ni][1], EPSF)));
        }

    #pragma unroll
    for (int mi = 0; mi < 2; mi++)
        #pragma unroll
        for (int h = 0; h < 2; h++) {
            float v = rs[mi][h];
            v += __shfl_xor_sync(0xffffffffu, v, 1);
            v += __shfl_xor_sync(0xffffffffu, v, 2);
            if (tg == 0) epi[warpM * 32 + mi * 16 + g + h * 8][warpN] = v;
        }
    __syncthreads();
    if (tid < 128) {
        float tot = epi[tid][0] + epi[tid][1];
        g_partial[(size_t)(mBase + tid) * NBLK + blockIdx.x] = tot;
    }
}

// ---------------- kernel 4: final deterministic reduction ----------------
__global__ void finalize(float* __restrict__ out) {
    float local = 0.f;
    for (int r = threadIdx.x; r < M_ROWS; r += 256) {
        const float* p = g_partial + (size_t)r * NBLK;
        float s = 0.f;
        #pragma unroll
        for (int j = 0; j < NBLK; j++) s += p[j];
        local += logf(s) - g_sim[r];
    }
    #pragma unroll
    for (int o = 16; o > 0; o >>= 1) local += __shfl_down_sync(0xffffffffu, local, o);
    __shared__ float red[8];
    int w = threadIdx.x >> 5, l = threadIdx.x & 31;
    if (l == 0) red[w] = local;
    __syncthreads();
    if (threadIdx.x == 0) {
        float tot = 0.f;
        #pragma unroll
        for (int i = 0; i < 8; i++) tot += red[i];
        out[0] = tot * (1.0f / (float)M_ROWS);
    }
}

// ---------------- launch ----------------
extern "C" void kernel_launch(void* const* d_in, const int* in_sizes, int n_in,
                              void* d_out, int out_size) {
    const float* x   = (const float*)d_in[0];
    const float* pos = (const float*)d_in[1];
    const float* neg = (const float*)d_in[2];

    prep_xp<<<M_ROWS, 256>>>(x, pos);
    prep_neg<<<N_ROWS, 256>>>(neg);
    dim3 grid(NBLK, M_ROWS / 128);   // (64, 32)
    gemm_fused<<<grid, 256>>>();
    finalize<<<1, 256>>>((float*)d_out);
}

// round 7
// speedup vs baseline: 1.5300x; 1.5300x over previous
#include <cuda_runtime.h>
#include <cuda_bf16.h>
#include <cstdint>

// Problem shape: x[4096,1024], positive[4096,1024], negative[8192,1024]
#define M_ROWS 4096
#define N_ROWS 8192
#define DIM    1024
#define EPSF   1e-8f
#define NBLK   (N_ROWS / 128)   // 64 column tiles
#define NPART  NBLK

// ---------------- scratch (no allocations allowed) ----------------
__device__ uint8_t g_Xf8[(size_t)M_ROWS * DIM];   // 4 MB  e4m3
__device__ uint8_t g_Nf8[(size_t)N_ROWS * DIM];   // 8 MB  e4m3
__device__ float g_nx[M_ROWS];
__device__ float g_sim[M_ROWS];
__device__ float g_rnn[N_ROWS];                    // 1/norm(neg)
__device__ float g_partial[(size_t)M_ROWS * NPART];
__device__ float g_rowloss[M_ROWS];

__device__ __forceinline__ uint32_t smem_u32(const void* p) {
    return (uint32_t)__cvta_generic_to_shared(p);
}

// pack 4 floats -> 4 e4m3 bytes (b0 = v0)
__device__ __forceinline__ uint32_t pack_e4m3x4(float v0, float v1, float v2, float v3) {
    uint32_t pk;
    asm("{\n\t.reg .b16 lo, hi;\n\t"
        "cvt.rn.satfinite.e4m3x2.f32 lo, %2, %1;\n\t"   // a->upper byte, b->lower
        "cvt.rn.satfinite.e4m3x2.f32 hi, %4, %3;\n\t"
        "mov.b32 %0, {lo, hi};\n\t}"
        : "=r"(pk) : "f"(v0), "f"(v1), "f"(v2), "f"(v3));
    return pk;
}

// ---------------- kernel 1: norms of x & positive, sim, x->fp8 ----------------
__global__ void prep_xp(const float* __restrict__ x, const float* __restrict__ p) {
    int row = blockIdx.x;
    int t = threadIdx.x;                       // 256 threads, 4 floats each
    const float4 xv = ((const float4*)(x + (size_t)row * DIM))[t];
    const float4 pv = ((const float4*)(p + (size_t)row * DIM))[t];

    ((uint32_t*)(g_Xf8 + (size_t)row * DIM))[t] = pack_e4m3x4(xv.x, xv.y, xv.z, xv.w);

    float sx = xv.x * xv.x + xv.y * xv.y + xv.z * xv.z + xv.w * xv.w;
    float sp = pv.x * pv.x + pv.y * pv.y + pv.z * pv.z + pv.w * pv.w;
    float dp = xv.x * pv.x + xv.y * pv.y + xv.z * pv.z + xv.w * pv.w;

    #pragma unroll
    for (int o = 16; o > 0; o >>= 1) {
        sx += __shfl_down_sync(0xffffffffu, sx, o);
        sp += __shfl_down_sync(0xffffffffu, sp, o);
        dp += __shfl_down_sync(0xffffffffu, dp, o);
    }
    __shared__ float ssx[8], ssp[8], sdp[8];
    int w = t >> 5, l = t & 31;
    if (l == 0) { ssx[w] = sx; ssp[w] = sp; sdp[w] = dp; }
    __syncthreads();
    if (t == 0) {
        float ax = 0.f, ap = 0.f, ad = 0.f;
        #pragma unroll
        for (int i = 0; i < 8; i++) { ax += ssx[i]; ap += ssp[i]; ad += sdp[i]; }
        float nx = sqrtf(ax), np = sqrtf(ap);
        g_nx[row]  = nx;
        g_sim[row] = ad / fmaxf(nx * np, EPSF);
    }
}

// ---------------- kernel 2: norms of negative, negative->fp8 ----------------
__global__ void prep_neg(const float* __restrict__ n) {
    int row = blockIdx.x;
    int t = threadIdx.x;
    const float4 nv = ((const float4*)(n + (size_t)row * DIM))[t];

    ((uint32_t*)(g_Nf8 + (size_t)row * DIM))[t] = pack_e4m3x4(nv.x, nv.y, nv.z, nv.w);

    float sn = nv.x * nv.x + nv.y * nv.y + nv.z * nv.z + nv.w * nv.w;
    #pragma unroll
    for (int o = 16; o > 0; o >>= 1) sn += __shfl_down_sync(0xffffffffu, sn, o);
    __shared__ float ssn[8];
    int w = t >> 5, l = t & 31;
    if (l == 0) ssn[w] = sn;
    __syncthreads();
    if (t == 0) {
        float a = 0.f;
        #pragma unroll
        for (int i = 0; i < 8; i++) a += ssn[i];
        g_rnn[row] = rsqrtf(a);
    }
}

// ---------------- kernel 3: fused FP8 GEMM + exp-rowsum epilogue ----------------
// C = Xf8 (4096x1024) @ Nf8^T via mma.sync.m16n8k32.e4m3. Block 128x128, BK=64,
// 8 warps (4m x 2n), warp tile 32x64. Smem rows padded to 80 B (conflict-free ldmatrix).
#define BK 64
#define LDB 80                   // bytes per smem row

__global__ void __launch_bounds__(256, 2) gemm_fused() {
    __shared__ uint8_t As[2][128 * LDB];
    __shared__ uint8_t Bs[2][128 * LDB];
    __shared__ float epi[128][2];

    const int tid = threadIdx.x;
    const int mBase = blockIdx.y * 128;
    const int nBase = blockIdx.x * 128;

    // cp.async mapping: 512 16B-chunks per tile (128 rows x 4 chunks), 2 iters per array
    const int lrow = tid >> 2;            // 0..63
    const int lchk = tid & 3;             // chunk within row (16B each)
    const uint8_t* srcA0 = g_Xf8 + (size_t)(mBase + lrow) * DIM + lchk * 16;
    const uint8_t* srcB0 = g_Nf8 + (size_t)(nBase + lrow) * DIM + lchk * 16;

    const int warp = tid >> 5, lane = tid & 31;
    const int warpM = warp >> 1, warpN = warp & 1;
    const int g = lane >> 2, tg = lane & 3;

    float acc[2][8][4];
    #pragma unroll
    for (int mi = 0; mi < 2; mi++)
        #pragma unroll
        for (int ni = 0; ni < 8; ni++)
            #pragma unroll
            for (int q = 0; q < 4; q++) acc[mi][ni][q] = 0.f;

    // ldmatrix lane offsets (stage/k-independent)
    // A x4: m0 rows0-7 k0-15 | m1 rows8-15 k0-15 | m2 rows0-7 k16-31 | m3 rows8-15 k16-31
    const int aRow = warpM * 32 + (lane & 15);
    const int aCol = (lane >> 4) << 4;            // 0 or 16 bytes
    // B x4: m0 n0-7 k0-15 | m1 n0-7 k16-31 | m2 n8-15 k0-15 | m3 n8-15 k16-31
    const int bRow = warpN * 64 + (lane & 7) + ((lane >> 4) << 3);
    const int bCol = ((lane >> 3) & 1) << 4;      // 0 or 16 bytes

    auto load_stage = [&](int s, int k0) {
        #pragma unroll
        for (int it = 0; it < 2; it++) {
            int r = lrow + it * 64;
            uint32_t da = smem_u32(&As[s][r * LDB + lchk * 16]);
            asm volatile("cp.async.cg.shared.global [%0], [%1], 16;\n"
                         :: "r"(da), "l"((const void*)(srcA0 + (size_t)it * 64 * DIM + k0)));
            uint32_t db = smem_u32(&Bs[s][r * LDB + lchk * 16]);
            asm volatile("cp.async.cg.shared.global [%0], [%1], 16;\n"
                         :: "r"(db), "l"((const void*)(srcB0 + (size_t)it * 64 * DIM + k0)));
        }
    };

    load_stage(0, 0);
    asm volatile("cp.async.commit_group;\n" ::);

    const int NK = DIM / BK;   // 16 k-tiles
    for (int k = 0; k < NK; k++) {
        asm volatile("cp.async.wait_group 0;\n" ::);
        __syncthreads();
        if (k + 1 < NK) {
            load_stage((k + 1) & 1, (k + 1) * BK);
            asm volatile("cp.async.commit_group;\n" ::);
        }
        const int s = k & 1;
        #pragma unroll
        for (int kk = 0; kk < BK; kk += 32) {     // 2 x k32 steps
            uint32_t ar[2][4];
            #pragma unroll
            for (int mi = 0; mi < 2; mi++) {
                uint32_t addr = smem_u32(&As[s][(aRow + mi * 16) * LDB + kk + aCol]);
                asm volatile("ldmatrix.sync.aligned.m8n8.x4.shared.b16 {%0,%1,%2,%3}, [%4];\n"
                             : "=r"(ar[mi][0]), "=r"(ar[mi][1]), "=r"(ar[mi][2]), "=r"(ar[mi][3])
                             : "r"(addr));
            }
            uint32_t br[8][2];
            #pragma unroll
            for (int nb = 0; nb < 4; nb++) {
                uint32_t addr = smem_u32(&Bs[s][(bRow + nb * 16) * LDB + kk + bCol]);
                uint32_t r0, r1, r2, r3;
                asm volatile("ldmatrix.sync.aligned.m8n8.x4.shared.b16 {%0,%1,%2,%3}, [%4];\n"
                             : "=r"(r0), "=r"(r1), "=r"(r2), "=r"(r3) : "r"(addr));
                br[2 * nb][0] = r0; br[2 * nb][1] = r1;      // n-block lo: b0(k0-15), b1(k16-31)
                br[2 * nb + 1][0] = r2; br[2 * nb + 1][1] = r3;  // n-block hi
            }
            #pragma unroll
            for (int mi = 0; mi < 2; mi++)
                #pragma unroll
                for (int ni = 0; ni < 8; ni++) {
                    float* d = acc[mi][ni];
                    asm volatile(
                        "mma.sync.aligned.m16n8k32.row.col.f32.e4m3.e4m3.f32 "
                        "{%0,%1,%2,%3}, {%4,%5,%6,%7}, {%8,%9}, {%0,%1,%2,%3};\n"
                        : "+f"(d[0]), "+f"(d[1]), "+f"(d[2]), "+f"(d[3])
                        : "r"(ar[mi][0]), "r"(ar[mi][1]), "r"(ar[mi][2]), "r"(ar[mi][3]),
                          "r"(br[ni][0]), "r"(br[ni][1]));
                }
        }
        __syncthreads();
    }

    // ---- epilogue: exp(cos) and per-row sum over this block's 128 columns ----
    float rxv[2][2];   // 1/nx per fragment row
    #pragma unroll
    for (int mi = 0; mi < 2; mi++) {
        int r0 = mBase + warpM * 32 + mi * 16 + g;
        rxv[mi][0] = 1.0f / g_nx[r0];
        rxv[mi][1] = 1.0f / g_nx[r0 + 8];
    }
    float rnv[8][2];   // 1/nn per fragment col
    #pragma unroll
    for (int ni = 0; ni < 8; ni++) {
        int c0 = nBase + warpN * 64 + ni * 8 + 2 * tg;
        rnv[ni][0] = g_rnn[c0];
        rnv[ni][1] = g_rnn[c0 + 1];
    }

    float rs[2][2] = {{0.f, 0.f}, {0.f, 0.f}};
    #pragma unroll
    for (int mi = 0; mi < 2; mi++)
        #pragma unroll
        for (int ni = 0; ni < 8; ni++) {
            const float* d = acc[mi][ni];
            rs[mi][0] += __expf(d[0] * rxv[mi][0] * rnv[ni][0])
                       + __expf(d[1] * rxv[mi][0] * rnv[ni][1]);
            rs[mi][1] += __expf(d[2] * rxv[mi][1] * rnv[ni][0])
                       + __expf(d[3] * rxv[mi][1] * rnv[ni][1]);
        }

    #pragma unroll
    for (int mi = 0; mi < 2; mi++)
        #pragma unroll
        for (int h = 0; h < 2; h++) {
            float v = rs[mi][h];
            v += __shfl_xor_sync(0xffffffffu, v, 1);
            v += __shfl_xor_sync(0xffffffffu, v, 2);
            if (tg == 0) epi[warpM * 32 + mi * 16 + g + h * 8][warpN] = v;
        }
    __syncthreads();
    if (tid < 128) {
        float tot = epi[tid][0] + epi[tid][1];
        g_partial[(size_t)(mBase + tid) * NPART + blockIdx.x] = tot;
    }
}

// ---------------- kernel 4a: per-row loss (warp per row) ----------------
__global__ void rowloss() {
    int row = (blockIdx.x * blockDim.x + threadIdx.x) >> 5;   // 0..4095
    int lane = threadIdx.x & 31;
    const float* p = g_partial + (size_t)row * NPART;
    float s = p[lane] + p[lane + 32];
    #pragma unroll
    for (int o = 16; o > 0; o >>= 1) s += __shfl_down_sync(0xffffffffu, s, o);
    if (lane == 0) g_rowloss[row] = logf(s) - g_sim[row];
}

// ---------------- kernel 4b: final deterministic reduction ----------------
__global__ void reduce_loss(float* __restrict__ out) {
    int t = threadIdx.x;
    const float4* p4 = (const float4*)g_rowloss;
    float local = 0.f;
    #pragma unroll
    for (int i = 0; i < 4; i++) {
        float4 v = p4[t + i * 256];
        local += v.x + v.y + v.z + v.w;
    }
    #pragma unroll
    for (int o = 16; o > 0; o >>= 1) local += __shfl_down_sync(0xffffffffu, local, o);
    __shared__ float red[8];
    int w = t >> 5, l = t & 31;
    if (l == 0) red[w] = local;
    __syncthreads();
    if (t == 0) {
        float tot = 0.f;
        #pragma unroll
        for (int i = 0; i < 8; i++) tot += red[i];
        out[0] = tot * (1.0f / (float)M_ROWS);
    }
}

// ---------------- launch ----------------
extern "C" void kernel_launch(void* const* d_in, const int* in_sizes, int n_in,
                              void* d_out, int out_size) {
    const float* x   = (const float*)d_in[0];
    const float* pos = (const float*)d_in[1];
    const float* neg = (const float*)d_in[2];

    prep_xp<<<M_ROWS, 256>>>(x, pos);
    prep_neg<<<N_ROWS, 256>>>(neg);
    dim3 grid(NBLK, M_ROWS / 128);   // (64, 32)
    gemm_fused<<<grid, 256>>>();
    rowloss<<<M_ROWS / 8, 256>>>();
    reduce_loss<<<1, 256>>>((float*)d_out);
}

// round 8
// speedup vs baseline: 1.5511x; 1.0138x over previous
#include <cuda_runtime.h>
#include <cuda_bf16.h>
#include <cstdint>

// Problem shape: x[4096,1024], positive[4096,1024], negative[8192,1024]
#define M_ROWS 4096
#define N_ROWS 8192
#define DIM    1024
#define EPSF   1e-8f

// GEMM tiling
#define BM 128
#define BN 256
#define BK 64
#define NK (DIM / BK)            // 16
#define NPART (N_ROWS / BN)      // 32 partials per row
#define LDB 80                   // padded smem row bytes (64 data + 16 pad): conflict-free ldmatrix
#define NSTAGE 4
#define A_STAGE (BM * LDB)       // 10240
#define B_STAGE (BN * LDB)       // 20480
#define STAGE (A_STAGE + B_STAGE) // 30720
#define DYN_SMEM (NSTAGE * STAGE) // 122880

// ---------------- scratch (no allocations allowed) ----------------
__device__ uint8_t g_Xf8[(size_t)M_ROWS * DIM];   // 4 MB  e4m3
__device__ uint8_t g_Nf8[(size_t)N_ROWS * DIM];   // 8 MB  e4m3
__device__ float g_rnx[M_ROWS];                    // 1/norm(x)
__device__ float g_sim[M_ROWS];
__device__ float g_rnn[N_ROWS];                    // 1/norm(neg)
__device__ float g_partial[(size_t)M_ROWS * NPART];
__device__ float g_rowloss[M_ROWS];

__device__ __forceinline__ uint32_t smem_u32(const void* p) {
    return (uint32_t)__cvta_generic_to_shared(p);
}

// pack 4 floats -> 4 e4m3 bytes (byte0 = v0)
__device__ __forceinline__ uint32_t pack_e4m3x4(float v0, float v1, float v2, float v3) {
    uint32_t pk;
    asm("{\n\t.reg .b16 lo, hi;\n\t"
        "cvt.rn.satfinite.e4m3x2.f32 lo, %2, %1;\n\t"
        "cvt.rn.satfinite.e4m3x2.f32 hi, %4, %3;\n\t"
        "mov.b32 %0, {lo, hi};\n\t}"
        : "=r"(pk) : "f"(v0), "f"(v1), "f"(v2), "f"(v3));
    return pk;
}

// ---------------- kernel 1: merged prep (x/pos norms + sim + fp8; neg norms + fp8) ----------------
__global__ void prep_all(const float* __restrict__ x, const float* __restrict__ p,
                         const float* __restrict__ n) {
    int b = blockIdx.x;
    int t = threadIdx.x;
    int w = t >> 5, l = t & 31;
    __shared__ float s0[8], s1[8], s2[8];

    if (b < M_ROWS) {
        int row = b;
        const float4 xv = ((const float4*)(x + (size_t)row * DIM))[t];
        const float4 pv = ((const float4*)(p + (size_t)row * DIM))[t];
        ((uint32_t*)(g_Xf8 + (size_t)row * DIM))[t] = pack_e4m3x4(xv.x, xv.y, xv.z, xv.w);

        float sx = xv.x * xv.x + xv.y * xv.y + xv.z * xv.z + xv.w * xv.w;
        float sp = pv.x * pv.x + pv.y * pv.y + pv.z * pv.z + pv.w * pv.w;
        float dp = xv.x * pv.x + xv.y * pv.y + xv.z * pv.z + xv.w * pv.w;
        #pragma unroll
        for (int o = 16; o > 0; o >>= 1) {
            sx += __shfl_down_sync(0xffffffffu, sx, o);
            sp += __shfl_down_sync(0xffffffffu, sp, o);
            dp += __shfl_down_sync(0xffffffffu, dp, o);
        }
        if (l == 0) { s0[w] = sx; s1[w] = sp; s2[w] = dp; }
        __syncthreads();
        if (t == 0) {
            float ax = 0.f, ap = 0.f, ad = 0.f;
            #pragma unroll
            for (int i = 0; i < 8; i++) { ax += s0[i]; ap += s1[i]; ad += s2[i]; }
            float nx = sqrtf(ax), np = sqrtf(ap);
            g_rnx[row] = 1.0f / nx;
            g_sim[row] = ad / fmaxf(nx * np, EPSF);
        }
    } else {
        int row = b - M_ROWS;
        const float4 nv = ((const float4*)(n + (size_t)row * DIM))[t];
        ((uint32_t*)(g_Nf8 + (size_t)row * DIM))[t] = pack_e4m3x4(nv.x, nv.y, nv.z, nv.w);

        float sn = nv.x * nv.x + nv.y * nv.y + nv.z * nv.z + nv.w * nv.w;
        #pragma unroll
        for (int o = 16; o > 0; o >>= 1) sn += __shfl_down_sync(0xffffffffu, sn, o);
        if (l == 0) s0[w] = sn;
        __syncthreads();
        if (t == 0) {
            float a = 0.f;
            #pragma unroll
            for (int i = 0; i < 8; i++) a += s0[i];
            g_rnn[row] = rsqrtf(a);
        }
    }
}

// ---------------- kernel 2: fused FP8 GEMM (128x256, 4-stage) + exp-rowsum epilogue ----------------
__global__ void __launch_bounds__(256, 1) gemm_fused() {
    extern __shared__ uint8_t dsm[];
    __shared__ float epi[128][2];
    __shared__ float s_rnn[BN];

    const int tid = threadIdx.x;
    const int mBase = blockIdx.y * BM;
    const int nBase = blockIdx.x * BN;

    s_rnn[tid] = g_rnn[nBase + tid];

    // cp.async mapping: A 512 chunks (128r x 4c of 16B), B 1024 chunks (256r x 4c)
    const int crow = tid >> 2;                  // 0..63
    const int cchk = (tid & 3) * 16;            // byte offset of chunk
    const uint8_t* srcA0 = g_Xf8 + (size_t)(mBase + crow) * DIM + (tid & 3) * 16;
    const uint8_t* srcB0 = g_Nf8 + (size_t)(nBase + crow) * DIM + (tid & 3) * 16;

    const int warp = tid >> 5, lane = tid & 31;
    const int warpM = warp >> 1, warpN = warp & 1;
    const int g = lane >> 2, tg = lane & 3;

    float acc[2][16][4];
    #pragma unroll
    for (int mi = 0; mi < 2; mi++)
        #pragma unroll
        for (int ni = 0; ni < 16; ni++)
            #pragma unroll
            for (int q = 0; q < 4; q++) acc[mi][ni][q] = 0.f;

    // ldmatrix lane offsets
    const int aRow = warpM * 32 + (lane & 15);
    const int aCol = (lane >> 4) << 4;               // 0 / 16
    const int bRow = warpN * 128 + (lane & 7) + ((lane >> 4) << 3);
    const int bCol = ((lane >> 3) & 1) << 4;         // 0 / 16

    auto load_stage = [&](int s, int k0) {
        const uint32_t aoff = smem_u32(dsm) + s * STAGE;
        const uint32_t boff = aoff + A_STAGE;
        #pragma unroll
        for (int it = 0; it < 2; it++) {             // A: rows crow, crow+64
            int r = crow + it * 64;
            asm volatile("cp.async.cg.shared.global [%0], [%1], 16;\n"
                         :: "r"(aoff + r * LDB + cchk),
                            "l"((const void*)(srcA0 + (size_t)it * 64 * DIM + k0)));
        }
        #pragma unroll
        for (int it = 0; it < 4; it++) {             // B: rows crow + it*64
            int r = crow + it * 64;
            asm volatile("cp.async.cg.shared.global [%0], [%1], 16;\n"
                         :: "r"(boff + r * LDB + cchk),
                            "l"((const void*)(srcB0 + (size_t)it * 64 * DIM + k0)));
        }
        asm volatile("cp.async.commit_group;\n" ::);
    };

    load_stage(0, 0);
    load_stage(1, BK);
    load_stage(2, 2 * BK);

    for (int t = 0; t < NK; t++) {
        asm volatile("cp.async.wait_group 2;\n" ::);
        __syncthreads();
        if (t + 3 < NK) load_stage((t + 3) & 3, (t + 3) * BK);

        const uint32_t aoff = smem_u32(dsm) + (t & 3) * STAGE;
        const uint32_t boff = aoff + A_STAGE;
        #pragma unroll
        for (int kk = 0; kk < BK; kk += 32) {
            uint32_t ar[2][4];
            #pragma unroll
            for (int mi = 0; mi < 2; mi++) {
                uint32_t addr = aoff + (aRow + mi * 16) * LDB + kk + aCol;
                asm volatile("ldmatrix.sync.aligned.m8n8.x4.shared.b16 {%0,%1,%2,%3}, [%4];\n"
                             : "=r"(ar[mi][0]), "=r"(ar[mi][1]), "=r"(ar[mi][2]), "=r"(ar[mi][3])
                             : "r"(addr));
            }
            #pragma unroll
            for (int nb = 0; nb < 8; nb++) {
                uint32_t addr = boff + (bRow + nb * 16) * LDB + kk + bCol;
                uint32_t r0, r1, r2, r3;
                asm volatile("ldmatrix.sync.aligned.m8n8.x4.shared.b16 {%0,%1,%2,%3}, [%4];\n"
                             : "=r"(r0), "=r"(r1), "=r"(r2), "=r"(r3) : "r"(addr));
                #pragma unroll
                for (int mi = 0; mi < 2; mi++) {
                    float* d0 = acc[mi][2 * nb];
                    asm volatile(
                        "mma.sync.aligned.m16n8k32.row.col.f32.e4m3.e4m3.f32 "
                        "{%0,%1,%2,%3}, {%4,%5,%6,%7}, {%8,%9}, {%0,%1,%2,%3};\n"
                        : "+f"(d0[0]), "+f"(d0[1]), "+f"(d0[2]), "+f"(d0[3])
                        : "r"(ar[mi][0]), "r"(ar[mi][1]), "r"(ar[mi][2]), "r"(ar[mi][3]),
                          "r"(r0), "r"(r1));
                    float* d1 = acc[mi][2 * nb + 1];
                    asm volatile(
                        "mma.sync.aligned.m16n8k32.row.col.f32.e4m3.e4m3.f32 "
                        "{%0,%1,%2,%3}, {%4,%5,%6,%7}, {%8,%9}, {%0,%1,%2,%3};\n"
                        : "+f"(d1[0]), "+f"(d1[1]), "+f"(d1[2]), "+f"(d1[3])
                        : "r"(ar[mi][0]), "r"(ar[mi][1]), "r"(ar[mi][2]), "r"(ar[mi][3]),
                          "r"(r2), "r"(r3));
                }
            }
        }
    }

    // ---- epilogue: exp(cos) + per-row sum over this block's 256 columns ----
    float rxv[2][2];
    #pragma unroll
    for (int mi = 0; mi < 2; mi++) {
        int r0 = mBase + warpM * 32 + mi * 16 + g;
        rxv[mi][0] = g_rnx[r0];
        rxv[mi][1] = g_rnx[r0 + 8];
    }

    float rs[2][2] = {{0.f, 0.f}, {0.f, 0.f}};
    #pragma unroll
    for (int ni = 0; ni < 16; ni++) {
        int c0 = warpN * 128 + ni * 8 + 2 * tg;
        float rn0 = s_rnn[c0], rn1 = s_rnn[c0 + 1];
        #pragma unroll
        for (int mi = 0; mi < 2; mi++) {
            const float* d = acc[mi][ni];
            rs[mi][0] += __expf(d[0] * rxv[mi][0] * rn0)
                       + __expf(d[1] * rxv[mi][0] * rn1);
            rs[mi][1] += __expf(d[2] * rxv[mi][1] * rn0)
                       + __expf(d[3] * rxv[mi][1] * rn1);
        }
    }

    #pragma unroll
    for (int mi = 0; mi < 2; mi++)
        #pragma unroll
        for (int h = 0; h < 2; h++) {
            float v = rs[mi][h];
            v += __shfl_xor_sync(0xffffffffu, v, 1);
            v += __shfl_xor_sync(0xffffffffu, v, 2);
            if (tg == 0) epi[warpM * 32 + mi * 16 + g + h * 8][warpN] = v;
        }
    __syncthreads();
    if (tid < 128) {
        float tot = epi[tid][0] + epi[tid][1];
        g_partial[(size_t)(mBase + tid) * NPART + blockIdx.x] = tot;
    }
}

// ---------------- kernel 3: per-row loss (warp per row) ----------------
__global__ void rowloss() {
    int row = (blockIdx.x * blockDim.x + threadIdx.x) >> 5;   // 0..4095
    int lane = threadIdx.x & 31;
    float s = g_partial[(size_t)row * NPART + lane];
    #pragma unroll
    for (int o = 16; o > 0; o >>= 1) s += __shfl_down_sync(0xffffffffu, s, o);
    if (lane == 0) g_rowloss[row] = logf(s) - g_sim[row];
}

// ---------------- kernel 4: final deterministic reduction ----------------
__global__ void reduce_loss(float* __restrict__ out) {
    int t = threadIdx.x;
    const float4* p4 = (const float4*)g_rowloss;
    float local = 0.f;
    #pragma unroll
    for (int i = 0; i < 4; i++) {
        float4 v = p4[t + i * 256];
        local += v.x + v.y + v.z + v.w;
    }
    #pragma unroll
    for (int o = 16; o > 0; o >>= 1) local += __shfl_down_sync(0xffffffffu, local, o);
    __shared__ float red[8];
    int w = t >> 5, l = t & 31;
    if (l == 0) red[w] = local;
    __syncthreads();
    if (t == 0) {
        float tot = 0.f;
        #pragma unroll
        for (int i = 0; i < 8; i++) tot += red[i];
        out[0] = tot * (1.0f / (float)M_ROWS);
    }
}

// ---------------- launch ----------------
extern "C" void kernel_launch(void* const* d_in, const int* in_sizes, int n_in,
                              void* d_out, int out_size) {
    const float* x   = (const float*)d_in[0];
    const float* pos = (const float*)d_in[1];
    const float* neg = (const float*)d_in[2];

    static bool attr_set = false;
    if (!attr_set) {
        cudaFuncSetAttribute(gemm_fused, cudaFuncAttributeMaxDynamicSharedMemorySize, DYN_SMEM);
        attr_set = true;
    }

    prep_all<<<M_ROWS + N_ROWS, 256>>>(x, pos, neg);
    dim3 grid(N_ROWS / BN, M_ROWS / BM);   // (32, 32)
    gemm_fused<<<grid, 256, DYN_SMEM>>>();
    rowloss<<<M_ROWS / 8, 256>>>();
    reduce_loss<<<1, 256>>>((float*)d_out);
}

// round 10
// speedup vs baseline: 1.7424x; 1.1233x over previous
#include <cuda_runtime.h>
#include <cuda_bf16.h>
#include <cuda_fp16.h>
#include <cstdint>

// Problem shape: x[4096,1024], positive[4096,1024], negative[8192,1024]
#define M_ROWS 4096
#define N_ROWS 8192
#define DIM    1024
#define EPSF   1e-8f

// GEMM tiling
#define BM 128
#define BN 256
#define BK 64
#define NK (DIM / BK)            // 16
#define NPART (N_ROWS / BN)      // 32 partials per row
#define LDB 80                   // padded smem row bytes: conflict-free ldmatrix
#define NSTAGE 3
#define A_STAGE (BM * LDB)       // 10240
#define B_STAGE (BN * LDB)       // 20480
#define STAGE (A_STAGE + B_STAGE) // 30720
#define DYN_SMEM (NSTAGE * STAGE) // 92160

// ---------------- scratch (no allocations allowed) ----------------
__device__ uint8_t g_Xf8[(size_t)M_ROWS * DIM];   // 4 MB  e4m3
__device__ uint8_t g_Nf8[(size_t)N_ROWS * DIM];   // 8 MB  e4m3
__device__ float g_rnx[M_ROWS];                    // 1/norm(x)
__device__ float g_sim[M_ROWS];
__device__ float g_rnn[N_ROWS];                    // 1/norm(neg)
__device__ float g_partial[(size_t)M_ROWS * NPART];
__device__ float g_rowloss[M_ROWS];

__device__ __forceinline__ uint32_t smem_u32(const void* p) {
    return (uint32_t)__cvta_generic_to_shared(p);
}

// pack 4 floats -> 4 e4m3 bytes (byte0 = v0)
__device__ __forceinline__ uint32_t pack_e4m3x4(float v0, float v1, float v2, float v3) {
    uint32_t pk;
    asm("{\n\t.reg .b16 lo, hi;\n\t"
        "cvt.rn.satfinite.e4m3x2.f32 lo, %2, %1;\n\t"
        "cvt.rn.satfinite.e4m3x2.f32 hi, %4, %3;\n\t"
        "mov.b32 %0, {lo, hi};\n\t}"
        : "=r"(pk) : "f"(v0), "f"(v1), "f"(v2), "f"(v3));
    return pk;
}

// ---------------- kernel 1: merged prep ----------------
__global__ void prep_all(const float* __restrict__ x, const float* __restrict__ p,
                         const float* __restrict__ n) {
    int b = blockIdx.x;
    int t = threadIdx.x;
    int w = t >> 5, l = t & 31;
    __shared__ float s0[8], s1[8], s2[8];

    if (b < M_ROWS) {
        int row = b;
        const float4 xv = ((const float4*)(x + (size_t)row * DIM))[t];
        const float4 pv = ((const float4*)(p + (size_t)row * DIM))[t];
        ((uint32_t*)(g_Xf8 + (size_t)row * DIM))[t] = pack_e4m3x4(xv.x, xv.y, xv.z, xv.w);

        float sx = xv.x * xv.x + xv.y * xv.y + xv.z * xv.z + xv.w * xv.w;
        float sp = pv.x * pv.x + pv.y * pv.y + pv.z * pv.z + pv.w * pv.w;
        float dp = xv.x * pv.x + xv.y * pv.y + xv.z * pv.z + xv.w * pv.w;
        #pragma unroll
        for (int o = 16; o > 0; o >>= 1) {
            sx += __shfl_down_sync(0xffffffffu, sx, o);
            sp += __shfl_down_sync(0xffffffffu, sp, o);
            dp += __shfl_down_sync(0xffffffffu, dp, o);
        }
        if (l == 0) { s0[w] = sx; s1[w] = sp; s2[w] = dp; }
        __syncthreads();
        if (t == 0) {
            float ax = 0.f, ap = 0.f, ad = 0.f;
            #pragma unroll
            for (int i = 0; i < 8; i++) { ax += s0[i]; ap += s1[i]; ad += s2[i]; }
            float nx = sqrtf(ax), np = sqrtf(ap);
            g_rnx[row] = 1.0f / nx;
            g_sim[row] = ad / fmaxf(nx * np, EPSF);
        }
    } else {
        int row = b - M_ROWS;
        const float4 nv = ((const float4*)(n + (size_t)row * DIM))[t];
        ((uint32_t*)(g_Nf8 + (size_t)row * DIM))[t] = pack_e4m3x4(nv.x, nv.y, nv.z, nv.w);

        float sn = nv.x * nv.x + nv.y * nv.y + nv.z * nv.z + nv.w * nv.w;
        #pragma unroll
        for (int o = 16; o > 0; o >>= 1) sn += __shfl_down_sync(0xffffffffu, sn, o);
        if (l == 0) s0[w] = sn;
        __syncthreads();
        if (t == 0) {
            float a = 0.f;
            #pragma unroll
            for (int i = 0; i < 8; i++) a += s0[i];
            g_rnn[row] = rsqrtf(a);
        }
    }
}

// ---------------- kernel 2: fused FP8 GEMM (f16 accumulator) + exp-rowsum epilogue ----------------
__global__ void __launch_bounds__(256, 2) gemm_fused() {
    extern __shared__ uint8_t dsm[];
    __shared__ float epi[128][2];
    __shared__ float s_rnn[BN];

    const int tid = threadIdx.x;
    const int mBase = blockIdx.y * BM;
    const int nBase = blockIdx.x * BN;

    s_rnn[tid] = g_rnn[nBase + tid];

    const int crow = tid >> 2;                  // 0..63
    const int cchk = (tid & 3) * 16;
    const uint8_t* srcA0 = g_Xf8 + (size_t)(mBase + crow) * DIM + (tid & 3) * 16;
    const uint8_t* srcB0 = g_Nf8 + (size_t)(nBase + crow) * DIM + (tid & 3) * 16;

    const int warp = tid >> 5, lane = tid & 31;
    const int warpM = warp >> 1, warpN = warp & 1;
    const int g = lane >> 2, tg = lane & 3;

    // f16 accumulators: 2 b32 regs per 16x8 fragment
    uint32_t acc[2][16][2];
    #pragma unroll
    for (int mi = 0; mi < 2; mi++)
        #pragma unroll
        for (int ni = 0; ni < 16; ni++) { acc[mi][ni][0] = 0u; acc[mi][ni][1] = 0u; }

    const int aRow = warpM * 32 + (lane & 15);
    const int aCol = (lane >> 4) << 4;
    const int bRow = warpN * 128 + (lane & 7) + ((lane >> 4) << 3);
    const int bCol = ((lane >> 3) & 1) << 4;

    auto load_stage = [&](int s, int k0) {
        const uint32_t aoff = smem_u32(dsm) + s * STAGE;
        const uint32_t boff = aoff + A_STAGE;
        #pragma unroll
        for (int it = 0; it < 2; it++) {
            int r = crow + it * 64;
            asm volatile("cp.async.cg.shared.global [%0], [%1], 16;\n"
                         :: "r"(aoff + r * LDB + cchk),
                            "l"((const void*)(srcA0 + (size_t)it * 64 * DIM + k0)));
        }
        #pragma unroll
        for (int it = 0; it < 4; it++) {
            int r = crow + it * 64;
            asm volatile("cp.async.cg.shared.global [%0], [%1], 16;\n"
                         :: "r"(boff + r * LDB + cchk),
                            "l"((const void*)(srcB0 + (size_t)it * 64 * DIM + k0)));
        }
        asm volatile("cp.async.commit_group;\n" ::);
    };

    load_stage(0, 0);
    load_stage(1, BK);

    for (int t = 0; t < NK; t++) {
        asm volatile("cp.async.wait_group 1;\n" ::);
        __syncthreads();
        if (t + 2 < NK) load_stage((t + 2) % NSTAGE, (t + 2) * BK);

        const uint32_t aoff = smem_u32(dsm) + (t % NSTAGE) * STAGE;
        const uint32_t boff = aoff + A_STAGE;
        #pragma unroll
        for (int kk = 0; kk < BK; kk += 32) {
            uint32_t ar[2][4];
            #pragma unroll
            for (int mi = 0; mi < 2; mi++) {
                uint32_t addr = aoff + (aRow + mi * 16) * LDB + kk + aCol;
                asm volatile("ldmatrix.sync.aligned.m8n8.x4.shared.b16 {%0,%1,%2,%3}, [%4];\n"
                             : "=r"(ar[mi][0]), "=r"(ar[mi][1]), "=r"(ar[mi][2]), "=r"(ar[mi][3])
                             : "r"(addr));
            }
            #pragma unroll
            for (int nb = 0; nb < 8; nb++) {
                uint32_t addr = boff + (bRow + nb * 16) * LDB + kk + bCol;
                uint32_t r0, r1, r2, r3;
                asm volatile("ldmatrix.sync.aligned.m8n8.x4.shared.b16 {%0,%1,%2,%3}, [%4];\n"
                             : "=r"(r0), "=r"(r1), "=r"(r2), "=r"(r3) : "r"(addr));
                #pragma unroll
                for (int mi = 0; mi < 2; mi++) {
                    uint32_t* d0 = acc[mi][2 * nb];
                    asm volatile(
                        "mma.sync.aligned.m16n8k32.row.col.f16.e4m3.e4m3.f16 "
                        "{%0,%1}, {%2,%3,%4,%5}, {%6,%7}, {%0,%1};\n"
                        : "+r"(d0[0]), "+r"(d0[1])
                        : "r"(ar[mi][0]), "r"(ar[mi][1]), "r"(ar[mi][2]), "r"(ar[mi][3]),
                          "r"(r0), "r"(r1));
                    uint32_t* d1 = acc[mi][2 * nb + 1];
                    asm volatile(
                        "mma.sync.aligned.m16n8k32.row.col.f16.e4m3.e4m3.f16 "
                        "{%0,%1}, {%2,%3,%4,%5}, {%6,%7}, {%0,%1};\n"
                        : "+r"(d1[0]), "+r"(d1[1])
                        : "r"(ar[mi][0]), "r"(ar[mi][1]), "r"(ar[mi][2]), "r"(ar[mi][3]),
                          "r"(r2), "r"(r3));
                }
            }
        }
    }

    // ---- epilogue: exp(cos) + per-row sum over this block's 256 columns ----
    float rxv[2][2];
    #pragma unroll
    for (int mi = 0; mi < 2; mi++) {
        int r0 = mBase + warpM * 32 + mi * 16 + g;
        rxv[mi][0] = g_rnx[r0];
        rxv[mi][1] = g_rnx[r0 + 8];
    }

    float rs[2][2] = {{0.f, 0.f}, {0.f, 0.f}};
    #pragma unroll
    for (int ni = 0; ni < 16; ni++) {
        int c0 = warpN * 128 + ni * 8 + 2 * tg;
        float rn0 = s_rnn[c0], rn1 = s_rnn[c0 + 1];
        #pragma unroll
        for (int mi = 0; mi < 2; mi++) {
            float2 lo = __half22float2(*(const __half2*)&acc[mi][ni][0]);  // row g:   c0, c1
            float2 hi = __half22float2(*(const __half2*)&acc[mi][ni][1]);  // row g+8: c0, c1
            rs[mi][0] += __expf(lo.x * rxv[mi][0] * rn0)
                       + __expf(lo.y * rxv[mi][0] * rn1);
            rs[mi][1] += __expf(hi.x * rxv[mi][1] * rn0)
                       + __expf(hi.y * rxv[mi][1] * rn1);
        }
    }

    #pragma unroll
    for (int mi = 0; mi < 2; mi++)
        #pragma unroll
        for (int h = 0; h < 2; h++) {
            float v = rs[mi][h];
            v += __shfl_xor_sync(0xffffffffu, v, 1);
            v += __shfl_xor_sync(0xffffffffu, v, 2);
            if (tg == 0) epi[warpM * 32 + mi * 16 + g + h * 8][warpN] = v;
        }
    __syncthreads();
    if (tid < 128) {
        float tot = epi[tid][0] + epi[tid][1];
        g_partial[(size_t)(mBase + tid) * NPART + blockIdx.x] = tot;
    }
}

// ---------------- kernel 3: per-row loss (warp per row) ----------------
__global__ void rowloss() {
    int row = (blockIdx.x * blockDim.x + threadIdx.x) >> 5;   // 0..4095
    int lane = threadIdx.x & 31;
    float s = g_partial[(size_t)row * NPART + lane];
    #pragma unroll
    for (int o = 16; o > 0; o >>= 1) s += __shfl_down_sync(0xffffffffu, s, o);
    if (lane == 0) g_rowloss[row] = logf(s) - g_sim[row];
}

// ---------------- kernel 4: final deterministic reduction ----------------
__global__ void reduce_loss(float* __restrict__ out) {
    int t = threadIdx.x;
    const float4* p4 = (const float4*)g_rowloss;
    float local = 0.f;
    #pragma unroll
    for (int i = 0; i < 4; i++) {
        float4 v = p4[t + i * 256];
        local += v.x + v.y + v.z + v.w;
    }
    #pragma unroll
    for (int o = 16; o > 0; o >>= 1) local += __shfl_down_sync(0xffffffffu, local, o);
    __shared__ float red[8];
    int w = t >> 5, l = t & 31;
    if (l == 0) red[w] = local;
    __syncthreads();
    if (t == 0) {
        float tot = 0.f;
        #pragma unroll
        for (int i = 0; i < 8; i++) tot += red[i];
        out[0] = tot * (1.0f / (float)M_ROWS);
    }
}

// ---------------- launch ----------------
extern "C" void kernel_launch(void* const* d_in, const int* in_sizes, int n_in,
                              void* d_out, int out_size) {
    const float* x   = (const float*)d_in[0];
    const float* pos = (const float*)d_in[1];
    const float* neg = (const float*)d_in[2];

    static bool attr_set = false;
    if (!attr_set) {
        cudaFuncSetAttribute(gemm_fused, cudaFuncAttributeMaxDynamicSharedMemorySize, DYN_SMEM);
        attr_set = true;
    }

    prep_all<<<M_ROWS + N_ROWS, 256>>>(x, pos, neg);
    dim3 grid(N_ROWS / BN, M_ROWS / BM);   // (32, 32)
    gemm_fused<<<grid, 256, DYN_SMEM>>>();
    rowloss<<<M_ROWS / 8, 256>>>();
    reduce_loss<<<1, 256>>>((float*)d_out);
}

// round 11
// speedup vs baseline: 1.7498x; 1.0042x over previous
#include <cuda_runtime.h>
#include <cuda_bf16.h>
#include <cuda_fp16.h>
#include <cstdint>

// Problem shape: x[4096,1024], positive[4096,1024], negative[8192,1024]
#define M_ROWS 4096
#define N_ROWS 8192
#define DIM    1024
#define EPSF   1e-8f

// GEMM tiling
#define BM 128
#define BN 256
#define BK 64
#define NK (DIM / BK)            // 16
#define NPART (N_ROWS / BN)      // 32 partials per row
#define LDB 80                   // padded smem row bytes: conflict-free ldmatrix
#define NSTAGE 3
#define A_STAGE (BM * LDB)       // 10240
#define B_STAGE (BN * LDB)       // 20480
#define STAGE (A_STAGE + B_STAGE) // 30720
#define DYN_SMEM (NSTAGE * STAGE) // 92160

// ---------------- scratch (no allocations allowed) ----------------
__device__ uint8_t g_Xf8[(size_t)M_ROWS * DIM];   // 4 MB  e4m3
__device__ uint8_t g_Nf8[(size_t)N_ROWS * DIM];   // 8 MB  e4m3
__device__ float g_rnx[M_ROWS];                    // 1/norm(x)
__device__ float g_sim[M_ROWS];
__device__ float g_rnn[N_ROWS];                    // 1/norm(neg)
__device__ float g_partial[(size_t)M_ROWS * NPART];
__device__ float g_rowloss[M_ROWS];

__device__ __forceinline__ uint32_t smem_u32(const void* p) {
    return (uint32_t)__cvta_generic_to_shared(p);
}

// pack 4 floats -> 4 e4m3 bytes (byte0 = v0)
__device__ __forceinline__ uint32_t pack_e4m3x4(float v0, float v1, float v2, float v3) {
    uint32_t pk;
    asm("{\n\t.reg .b16 lo, hi;\n\t"
        "cvt.rn.satfinite.e4m3x2.f32 lo, %2, %1;\n\t"
        "cvt.rn.satfinite.e4m3x2.f32 hi, %4, %3;\n\t"
        "mov.b32 %0, {lo, hi};\n\t}"
        : "=r"(pk) : "f"(v0), "f"(v1), "f"(v2), "f"(v3));
    return pk;
}

// ---------------- kernel 1: merged prep ----------------
__global__ void prep_all(const float* __restrict__ x, const float* __restrict__ p,
                         const float* __restrict__ n) {
    int b = blockIdx.x;
    int t = threadIdx.x;
    int w = t >> 5, l = t & 31;
    __shared__ float s0[8], s1[8], s2[8];

    if (b < M_ROWS) {
        int row = b;
        const float4 xv = ((const float4*)(x + (size_t)row * DIM))[t];
        const float4 pv = ((const float4*)(p + (size_t)row * DIM))[t];
        ((uint32_t*)(g_Xf8 + (size_t)row * DIM))[t] = pack_e4m3x4(xv.x, xv.y, xv.z, xv.w);

        float sx = xv.x * xv.x + xv.y * xv.y + xv.z * xv.z + xv.w * xv.w;
        float sp = pv.x * pv.x + pv.y * pv.y + pv.z * pv.z + pv.w * pv.w;
        float dp = xv.x * pv.x + xv.y * pv.y + xv.z * pv.z + xv.w * pv.w;
        #pragma unroll
        for (int o = 16; o > 0; o >>= 1) {
            sx += __shfl_down_sync(0xffffffffu, sx, o);
            sp += __shfl_down_sync(0xffffffffu, sp, o);
            dp += __shfl_down_sync(0xffffffffu, dp, o);
        }
        if (l == 0) { s0[w] = sx; s1[w] = sp; s2[w] = dp; }
        __syncthreads();
        if (t == 0) {
            float ax = 0.f, ap = 0.f, ad = 0.f;
            #pragma unroll
            for (int i = 0; i < 8; i++) { ax += s0[i]; ap += s1[i]; ad += s2[i]; }
            float nx = sqrtf(ax), np = sqrtf(ap);
            g_rnx[row] = 1.0f / nx;
            g_sim[row] = ad / fmaxf(nx * np, EPSF);
        }
    } else {
        int row = b - M_ROWS;
        const float4 nv = ((const float4*)(n + (size_t)row * DIM))[t];
        ((uint32_t*)(g_Nf8 + (size_t)row * DIM))[t] = pack_e4m3x4(nv.x, nv.y, nv.z, nv.w);

        float sn = nv.x * nv.x + nv.y * nv.y + nv.z * nv.z + nv.w * nv.w;
        #pragma unroll
        for (int o = 16; o > 0; o >>= 1) sn += __shfl_down_sync(0xffffffffu, sn, o);
        if (l == 0) s0[w] = sn;
        __syncthreads();
        if (t == 0) {
            float a = 0.f;
            #pragma unroll
            for (int i = 0; i < 8; i++) a += s0[i];
            g_rnn[row] = rsqrtf(a);
        }
    }
}

// ---------------- kernel 2: fused FP8 GEMM (f16 acc, 2x4 warp grid, 64x64 warp tile) ----------------
__global__ void __launch_bounds__(256, 2) gemm_fused() {
    extern __shared__ uint8_t dsm[];
    __shared__ float epi[128][4];
    __shared__ float s_rnn[BN];

    const int tid = threadIdx.x;
    const int mBase = blockIdx.y * BM;
    const int nBase = blockIdx.x * BN;

    s_rnn[tid] = g_rnn[nBase + tid];

    const int crow = tid >> 2;                  // 0..63
    const int cchk = (tid & 3) * 16;
    const uint8_t* srcA0 = g_Xf8 + (size_t)(mBase + crow) * DIM + (tid & 3) * 16;
    const uint8_t* srcB0 = g_Nf8 + (size_t)(nBase + crow) * DIM + (tid & 3) * 16;

    const int warp = tid >> 5, lane = tid & 31;
    const int warpM = warp >> 2;                // 0..1  (64 rows each)
    const int warpN = warp & 3;                 // 0..3  (64 cols each)
    const int g = lane >> 2, tg = lane & 3;

    // f16 accumulators: 4 m-frags x 8 n-frags x 2 b32
    uint32_t acc[4][8][2];
    #pragma unroll
    for (int mi = 0; mi < 4; mi++)
        #pragma unroll
        for (int ni = 0; ni < 8; ni++) { acc[mi][ni][0] = 0u; acc[mi][ni][1] = 0u; }

    const int aRow = warpM * 64 + (lane & 15);
    const int aCol = (lane >> 4) << 4;               // 0 / 16
    const int bRow = warpN * 64 + (lane & 7) + ((lane >> 4) << 3);
    const int bCol = ((lane >> 3) & 1) << 4;         // 0 / 16

    auto load_stage = [&](int s, int k0) {
        const uint32_t aoff = smem_u32(dsm) + s * STAGE;
        const uint32_t boff = aoff + A_STAGE;
        #pragma unroll
        for (int it = 0; it < 2; it++) {             // A: 128 rows
            int r = crow + it * 64;
            asm volatile("cp.async.cg.shared.global [%0], [%1], 16;\n"
                         :: "r"(aoff + r * LDB + cchk),
                            "l"((const void*)(srcA0 + (size_t)it * 64 * DIM + k0)));
        }
        #pragma unroll
        for (int it = 0; it < 4; it++) {             // B: 256 rows
            int r = crow + it * 64;
            asm volatile("cp.async.cg.shared.global [%0], [%1], 16;\n"
                         :: "r"(boff + r * LDB + cchk),
                            "l"((const void*)(srcB0 + (size_t)it * 64 * DIM + k0)));
        }
        asm volatile("cp.async.commit_group;\n" ::);
    };

    load_stage(0, 0);
    load_stage(1, BK);

    for (int t = 0; t < NK; t++) {
        asm volatile("cp.async.wait_group 1;\n" ::);
        __syncthreads();
        if (t + 2 < NK) load_stage((t + 2) % NSTAGE, (t + 2) * BK);

        const uint32_t aoff = smem_u32(dsm) + (t % NSTAGE) * STAGE;
        const uint32_t boff = aoff + A_STAGE;
        #pragma unroll
        for (int kk = 0; kk < BK; kk += 32) {
            uint32_t ar[4][4];
            #pragma unroll
            for (int mi = 0; mi < 4; mi++) {
                uint32_t addr = aoff + (aRow + mi * 16) * LDB + kk + aCol;
                asm volatile("ldmatrix.sync.aligned.m8n8.x4.shared.b16 {%0,%1,%2,%3}, [%4];\n"
                             : "=r"(ar[mi][0]), "=r"(ar[mi][1]), "=r"(ar[mi][2]), "=r"(ar[mi][3])
                             : "r"(addr));
            }
            #pragma unroll
            for (int nb = 0; nb < 4; nb++) {
                uint32_t addr = boff + (bRow + nb * 16) * LDB + kk + bCol;
                uint32_t r0, r1, r2, r3;
                asm volatile("ldmatrix.sync.aligned.m8n8.x4.shared.b16 {%0,%1,%2,%3}, [%4];\n"
                             : "=r"(r0), "=r"(r1), "=r"(r2), "=r"(r3) : "r"(addr));
                #pragma unroll
                for (int mi = 0; mi < 4; mi++) {
                    uint32_t* d0 = acc[mi][2 * nb];
                    asm volatile(
                        "mma.sync.aligned.m16n8k32.row.col.f16.e4m3.e4m3.f16 "
                        "{%0,%1}, {%2,%3,%4,%5}, {%6,%7}, {%0,%1};\n"
                        : "+r"(d0[0]), "+r"(d0[1])
                        : "r"(ar[mi][0]), "r"(ar[mi][1]), "r"(ar[mi][2]), "r"(ar[mi][3]),
                          "r"(r0), "r"(r1));
                    uint32_t* d1 = acc[mi][2 * nb + 1];
                    asm volatile(
                        "mma.sync.aligned.m16n8k32.row.col.f16.e4m3.e4m3.f16 "
                        "{%0,%1}, {%2,%3,%4,%5}, {%6,%7}, {%0,%1};\n"
                        : "+r"(d1[0]), "+r"(d1[1])
                        : "r"(ar[mi][0]), "r"(ar[mi][1]), "r"(ar[mi][2]), "r"(ar[mi][3]),
                          "r"(r2), "r"(r3));
                }
            }
        }
    }

    // ---- epilogue: exp(cos) + per-row sum over this block's 256 columns ----
    float rxv[4][2];
    #pragma unroll
    for (int mi = 0; mi < 4; mi++) {
        int r0 = mBase + warpM * 64 + mi * 16 + g;
        rxv[mi][0] = g_rnx[r0];
        rxv[mi][1] = g_rnx[r0 + 8];
    }

    float rs[4][2];
    #pragma unroll
    for (int mi = 0; mi < 4; mi++) { rs[mi][0] = 0.f; rs[mi][1] = 0.f; }

    #pragma unroll
    for (int ni = 0; ni < 8; ni++) {
        int c0 = warpN * 64 + ni * 8 + 2 * tg;
        float rn0 = s_rnn[c0], rn1 = s_rnn[c0 + 1];
        #pragma unroll
        for (int mi = 0; mi < 4; mi++) {
            float2 lo = __half22float2(*(const __half2*)&acc[mi][ni][0]);  // row g
            float2 hi = __half22float2(*(const __half2*)&acc[mi][ni][1]);  // row g+8
            rs[mi][0] += __expf(lo.x * rxv[mi][0] * rn0)
                       + __expf(lo.y * rxv[mi][0] * rn1);
            rs[mi][1] += __expf(hi.x * rxv[mi][1] * rn0)
                       + __expf(hi.y * rxv[mi][1] * rn1);
        }
    }

    #pragma unroll
    for (int mi = 0; mi < 4; mi++)
        #pragma unroll
        for (int h = 0; h < 2; h++) {
            float v = rs[mi][h];
            v += __shfl_xor_sync(0xffffffffu, v, 1);
            v += __shfl_xor_sync(0xffffffffu, v, 2);
            if (tg == 0) epi[warpM * 64 + mi * 16 + g + h * 8][warpN] = v;
        }
    __syncthreads();
    if (tid < 128) {
        float tot = (epi[tid][0] + epi[tid][1]) + (epi[tid][2] + epi[tid][3]);
        g_partial[(size_t)(mBase + tid) * NPART + blockIdx.x] = tot;
    }
}

// ---------------- kernel 3: per-row loss (warp per row) ----------------
__global__ void rowloss() {
    int row = (blockIdx.x * blockDim.x + threadIdx.x) >> 5;   // 0..4095
    int lane = threadIdx.x & 31;
    float s = g_partial[(size_t)row * NPART + lane];
    #pragma unroll
    for (int o = 16; o > 0; o >>= 1) s += __shfl_down_sync(0xffffffffu, s, o);
    if (lane == 0) g_rowloss[row] = logf(s) - g_sim[row];
}

// ---------------- kernel 4: final deterministic reduction ----------------
__global__ void reduce_loss(float* __restrict__ out) {
    int t = threadIdx.x;
    const float4* p4 = (const float4*)g_rowloss;
    float local = 0.f;
    #pragma unroll
    for (int i = 0; i < 4; i++) {
        float4 v = p4[t + i * 256];
        local += v.x + v.y + v.z + v.w;
    }
    #pragma unroll
    for (int o = 16; o > 0; o >>= 1) local += __shfl_down_sync(0xffffffffu, local, o);
    __shared__ float red[8];
    int w = t >> 5, l = t & 31;
    if (l == 0) red[w] = local;
    __syncthreads();
    if (t == 0) {
        float tot = 0.f;
        #pragma unroll
        for (int i = 0; i < 8; i++) tot += red[i];
        out[0] = tot * (1.0f / (float)M_ROWS);
    }
}

// ---------------- launch ----------------
extern "C" void kernel_launch(void* const* d_in, const int* in_sizes, int n_in,
                              void* d_out, int out_size) {
    const float* x   = (const float*)d_in[0];
    const float* pos = (const float*)d_in[1];
    const float* neg = (const float*)d_in[2];

    static bool attr_set = false;
    if (!attr_set) {
        cudaFuncSetAttribute(gemm_fused, cudaFuncAttributeMaxDynamicSharedMemorySize, DYN_SMEM);
        attr_set = true;
    }

    prep_all<<<M_ROWS + N_ROWS, 256>>>(x, pos, neg);
    dim3 grid(N_ROWS / BN, M_ROWS / BM);   // (32, 32)
    gemm_fused<<<grid, 256, DYN_SMEM>>>();
    rowloss<<<M_ROWS / 8, 256>>>();
    reduce_loss<<<1, 256>>>((float*)d_out);
}